// round 1
// baseline (speedup 1.0000x reference)
#include <cuda_runtime.h>

// Fast Hadamard Transform, DIM = 4096, fp32.
// One CTA per row. 256 threads, 16 elements per thread.
// Three FWHT-16 register passes over bit-groups {8..11}, {4..7}, {0..3},
// with two padded-SMEM transposes in between.

#define FWHT_DIM 4096
#define THREADS 256

// scale = 2^-(L(L+1)/4) with L=12 -> 2^-39
#define FWHT_SCALE 0x1p-39f

// Padded shared index: one float of pad per 16 -> conflict-free for
// patterns B (high*256 + j*16 + low) and C (t*16 + j); pattern A
// (j*256 + t) has a single 2-way pair per warp (acceptable).
__device__ __forceinline__ int sidx(int i) { return i + (i >> 4); }

__device__ __forceinline__ void fwht16(float r[16]) {
#pragma unroll
    for (int h = 1; h < 16; h <<= 1) {
#pragma unroll
        for (int k = 0; k < 16; k++) {
            if (!(k & h)) {
                float a = r[k];
                float b = r[k | h];
                r[k]     = a + b;
                r[k | h] = a - b;
            }
        }
    }
}

__global__ void __launch_bounds__(THREADS)
fwht4096_kernel(const float* __restrict__ x, float* __restrict__ out) {
    __shared__ float s[FWHT_DIM + (FWHT_DIM >> 4)];  // 4096 + 256 floats

    const int t = threadIdx.x;
    const size_t row_off = (size_t)blockIdx.x * FWHT_DIM;
    const float* __restrict__ xr = x + row_off;
    float* __restrict__ yr = out + row_off;

    float r[16];

    // ---- Stage 1: bits 8..11 (thread owns {j*256 + t}) ----
    // Coalesced: consecutive lanes -> consecutive 4B words, 16 independent loads.
#pragma unroll
    for (int j = 0; j < 16; j++) {
        r[j] = xr[j * 256 + t];
    }
    fwht16(r);

#pragma unroll
    for (int j = 0; j < 16; j++) {
        int i = j * 256 + t;
        s[sidx(i)] = r[j];
    }
    __syncthreads();

    // ---- Stage 2: bits 4..7 (thread owns {high*256 + j*16 + low}) ----
    {
        const int base = ((t >> 4) << 8) + (t & 15);
#pragma unroll
        for (int j = 0; j < 16; j++) {
            int i = base + j * 16;
            r[j] = s[sidx(i)];
        }
        fwht16(r);
#pragma unroll
        for (int j = 0; j < 16; j++) {
            int i = base + j * 16;
            s[sidx(i)] = r[j];
        }
    }
    __syncthreads();

    // ---- Stage 3: bits 0..3 (thread owns 16 contiguous elements {t*16 + j}) ----
    {
        const int base = t * 16;
        // phys(t*16 + j) = t*17 + j for j<16 -> stride-17 across lanes, conflict-free
#pragma unroll
        for (int j = 0; j < 16; j++) {
            r[j] = s[t * 17 + j];
        }
        fwht16(r);
#pragma unroll
        for (int j = 0; j < 16; j++) {
            r[j] *= FWHT_SCALE;
        }
        // Vectorized store: thread writes 64 contiguous bytes; warp writes 2 KiB.
        float4* o4 = reinterpret_cast<float4*>(yr + base);
        o4[0] = make_float4(r[0],  r[1],  r[2],  r[3]);
        o4[1] = make_float4(r[4],  r[5],  r[6],  r[7]);
        o4[2] = make_float4(r[8],  r[9],  r[10], r[11]);
        o4[3] = make_float4(r[12], r[13], r[14], r[15]);
    }
}

extern "C" void kernel_launch(void* const* d_in, const int* in_sizes, int n_in,
                              void* d_out, int out_size) {
    const float* x = (const float*)d_in[0];
    float* out = (float*)d_out;
    const int rows = in_sizes[0] / FWHT_DIM;  // 8192 for (4, 2048, 4096)
    fwht4096_kernel<<<rows, THREADS>>>(x, out);
}

// round 2
// speedup vs baseline: 1.4048x; 1.4048x over previous
#include <cuda_runtime.h>

// Fast Hadamard Transform, DIM = 4096, fp32 — single-SMEM-trip version.
//
// 64 threads per row, 64 elements per thread, two FWHT-64 register passes:
//   pass 1 over element bits {0,1,8,9,10,11}  (float4-coalesced loads)
//   pass 2 over element bits {2..7}           (one swizzled SMEM exchange)
// then a 3-bit register<->lane shuffle transpose (i[2..4] <-> i[8..10])
// to make the final stores fully coalesced.
//
// L1 data-path traffic per row: 16KB LDG + 16KB STS + 16KB LDS + 16KB STG
// (vs 96KB for the 2-trip variant).

#define FWHT_DIM 4096
#define ROWS_PER_CTA 2
#define THREADS (64 * ROWS_PER_CTA)   // 128

// scale = 2^-(L(L+1)/4) with L=12 -> 2^-39
#define FWHT_SCALE 0x1p-39f

__device__ __forceinline__ void fwht64(float r[64]) {
#pragma unroll
    for (int h = 1; h < 64; h <<= 1) {
#pragma unroll
        for (int k = 0; k < 64; k++) {
            if (!(k & h)) {
                float a = r[k];
                float b = r[k ^ h];
                r[k]     = a + b;
                r[k ^ h] = a - b;
            }
        }
    }
}

// Swap register-index bit `rb` with lane bit `lb`:
// data at (regbit=x, lanebit=y) moves to (regbit=y, lanebit=x).
#define SWAPBIT(r, lane, rb, lb)                                               \
    do {                                                                       \
        const unsigned _lm = 1u << (lb);                                       \
        const bool _hi = ((lane) & _lm) != 0;                                  \
        _Pragma("unroll")                                                      \
        for (int _k = 0; _k < 64; _k++) {                                      \
            if (!(_k & (1 << (rb)))) {                                         \
                const int _k2 = _k | (1 << (rb));                              \
                float _send = _hi ? (r)[_k] : (r)[_k2];                        \
                float _recv = __shfl_xor_sync(0xffffffffu, _send, _lm, 32);    \
                if (_hi) (r)[_k] = _recv; else (r)[_k2] = _recv;               \
            }                                                                  \
        }                                                                      \
    } while (0)

__global__ void __launch_bounds__(THREADS)
fwht4096_kernel(const float* __restrict__ x, float* __restrict__ out) {
    __shared__ float s[ROWS_PER_CTA * FWHT_DIM];   // 32 KB

    const int tid      = threadIdx.x;
    const int rowInCta = tid >> 6;       // which of the 2 rows
    const int t        = tid & 63;       // thread within row
    const int lane     = tid & 31;       // lane within warp
    const int w        = (t >> 5) & 1;   // warp within row (= element bit 11)

    const size_t row = (size_t)blockIdx.x * ROWS_PER_CTA + rowInCta;
    const float* __restrict__ xr = x + row * FWHT_DIM;
    float* __restrict__ yr = out + row * FWHT_DIM;
    float* __restrict__ sr = s + rowInCta * FWHT_DIM;

    float r[64];

    // ---- Pass 1: bits {0,1,8,9,10,11}. r[p*4+q] = x[p*256 + t*4 + q] ----
    // 16 independent LDG.128, fully coalesced (warp covers 512B per inst).
#pragma unroll
    for (int p = 0; p < 16; p++) {
        float4 v = *reinterpret_cast<const float4*>(xr + p * 256 + t * 4);
        r[p * 4 + 0] = v.x;
        r[p * 4 + 1] = v.y;
        r[p * 4 + 2] = v.z;
        r[p * 4 + 3] = v.w;
    }
    fwht64(r);   // reg index j = (p<<2)|q covers element bits {8..11,0,1}

    // ---- SMEM write: STS.128, XOR-swizzled (conflict-free) ----
    // float addr a = p*256 + t*4 + q ; phys = a ^ (((a>>8)&7)<<2) = a ^ ((p&7)<<2)
#pragma unroll
    for (int p = 0; p < 16; p++) {
        int a0   = p * 256 + t * 4;
        int phys = a0 ^ ((p & 7) << 2);
        *reinterpret_cast<float4*>(sr + phys) =
            make_float4(r[p * 4 + 0], r[p * 4 + 1], r[p * 4 + 2], r[p * 4 + 3]);
    }
    __syncthreads();

    // ---- SMEM read for pass 2: thread owns bits {2..7} varying ----
    // a = th*256 + j*4 + tl, th = t[5:2] = i[11:8], tl = t[1:0] = i[1:0]
    // phys = a ^ ((th&7)<<2): banks = ((j^th)[2:0]<<2)|tl -> all 32 distinct.
    {
        const int th    = t >> 2;
        const int tl    = t & 3;
        const int base2 = th * 256 + tl;
        const int c     = (th & 7) << 2;
#pragma unroll
        for (int j = 0; j < 64; j++) {
            r[j] = sr[base2 + ((j * 4) ^ c)];
        }
    }
    fwht64(r);   // reg index j' = i[7:2] covers element bits {2..7}

    // ---- Scale ----
#pragma unroll
    for (int j = 0; j < 64; j++) r[j] *= FWHT_SCALE;

    // ---- Shuffle transpose: swap i[2]<->i[8], i[3]<->i[9], i[4]<->i[10] ----
    // (reg-index bits 0,1,2  <->  lane bits 2,3,4)
    SWAPBIT(r, lane, 0, 2);
    SWAPBIT(r, lane, 1, 3);
    SWAPBIT(r, lane, 2, 4);

    // ---- Coalesced stores ----
    // Post-swap reg k: k[2:0] = i[10:8], k[5:3] = i[7:5]; lane = i[4:0]; w = i[11].
    // m = i[10:5] = ((k&7)<<3) | (k>>3).  Each STG.32 inst writes 128B contiguous.
    {
        float* __restrict__ yw = yr + w * 2048 + lane;
#pragma unroll
        for (int k = 0; k < 64; k++) {
            const int m = ((k & 7) << 3) | (k >> 3);
            yw[m * 32] = r[k];
        }
    }
}

extern "C" void kernel_launch(void* const* d_in, const int* in_sizes, int n_in,
                              void* d_out, int out_size) {
    const float* x = (const float*)d_in[0];
    float* out = (float*)d_out;
    const int rows = in_sizes[0] / FWHT_DIM;   // 8192
    fwht4096_kernel<<<rows / ROWS_PER_CTA, THREADS>>>(x, out);
}